// round 1
// baseline (speedup 1.0000x reference)
#include <cuda_runtime.h>
#include <cuda_bf16.h>
#include <math.h>

#define B_    4
#define S_    1024
#define E_    1024
#define H_    16
#define DH_   64

// ---------------- scratch (device globals; no allocation allowed) ----------------
__device__ float g_qn [B_ * S_ * E_];
__device__ float g_qp [B_ * S_ * E_];
__device__ float g_kp [B_ * S_ * E_];
__device__ float g_vp [B_ * S_ * E_];
__device__ float g_ctx[B_ * S_ * E_];

// ---------------- layernorm: one block per row of 1024 ----------------
__global__ __launch_bounds__(256) void ln_kernel(const float* __restrict__ x,
                                                 const float* __restrict__ gamma,
                                                 const float* __restrict__ beta,
                                                 float* __restrict__ y) {
    __shared__ float red[32];
    int row = blockIdx.x;
    int tid = threadIdx.x;
    const float* xr = x + (size_t)row * 1024;

    float v[4];
    float s = 0.f;
#pragma unroll
    for (int i = 0; i < 4; i++) { v[i] = xr[tid + 256 * i]; s += v[i]; }

    // block reduce sum
    for (int off = 16; off; off >>= 1) s += __shfl_xor_sync(0xffffffffu, s, off);
    int lane = tid & 31, wid = tid >> 5;
    if (lane == 0) red[wid] = s;
    __syncthreads();
    if (wid == 0) {
        float t = (lane < 8) ? red[lane] : 0.f;
        for (int off = 4; off; off >>= 1) t += __shfl_xor_sync(0xffffffffu, t, off);
        if (lane == 0) red[0] = t;
    }
    __syncthreads();
    float mean = red[0] * (1.f / 1024.f);
    __syncthreads();

    float vs = 0.f;
#pragma unroll
    for (int i = 0; i < 4; i++) { float d = v[i] - mean; vs += d * d; }
    for (int off = 16; off; off >>= 1) vs += __shfl_xor_sync(0xffffffffu, vs, off);
    if (lane == 0) red[wid] = vs;
    __syncthreads();
    if (wid == 0) {
        float t = (lane < 8) ? red[lane] : 0.f;
        for (int off = 4; off; off >>= 1) t += __shfl_xor_sync(0xffffffffu, t, off);
        if (lane == 0) red[0] = t;
    }
    __syncthreads();
    float var = red[0] * (1.f / 1024.f);
    float rstd = rsqrtf(var + 1e-5f);

    float* yr = y + (size_t)row * 1024;
#pragma unroll
    for (int i = 0; i < 4; i++) {
        int c = tid + 256 * i;
        yr[c] = (v[i] - mean) * rstd * gamma[c] + beta[c];
    }
}

// ---------------- plain SGEMM: C[M,N] = A[M,K] @ B[K,N], tiles 64x64x16 ----------------
__global__ __launch_bounds__(256) void sgemm_kernel(const float* __restrict__ A,
                                                    const float* __restrict__ Bm,
                                                    float* __restrict__ C,
                                                    int M, int N, int K) {
    __shared__ float As[16][64];
    __shared__ float Bs[16][64];
    int tid = threadIdx.x;
    int row0 = blockIdx.y * 64;
    int col0 = blockIdx.x * 64;
    int tx = tid & 15, ty = tid >> 4;

    int a_m = tid >> 2;
    int a_k = (tid & 3) << 2;
    int b_k = tid >> 4;
    int b_n = (tid & 15) << 2;

    float acc[4][4];
#pragma unroll
    for (int i = 0; i < 4; i++)
#pragma unroll
        for (int j = 0; j < 4; j++) acc[i][j] = 0.f;

    for (int k0 = 0; k0 < K; k0 += 16) {
        float4 a4 = *(const float4*)(A + (size_t)(row0 + a_m) * K + k0 + a_k);
        As[a_k + 0][a_m] = a4.x;
        As[a_k + 1][a_m] = a4.y;
        As[a_k + 2][a_m] = a4.z;
        As[a_k + 3][a_m] = a4.w;
        *(float4*)(&Bs[b_k][b_n]) = *(const float4*)(Bm + (size_t)(k0 + b_k) * N + col0 + b_n);
        __syncthreads();
#pragma unroll
        for (int k = 0; k < 16; k++) {
            float4 ra = *(const float4*)(&As[k][ty << 2]);
            float4 rb = *(const float4*)(&Bs[k][tx << 2]);
            float raa[4] = {ra.x, ra.y, ra.z, ra.w};
            float rbb[4] = {rb.x, rb.y, rb.z, rb.w};
#pragma unroll
            for (int i = 0; i < 4; i++)
#pragma unroll
                for (int j = 0; j < 4; j++) acc[i][j] += raa[i] * rbb[j];
        }
        __syncthreads();
    }
#pragma unroll
    for (int i = 0; i < 4; i++) {
        int r = row0 + (ty << 2) + i;
#pragma unroll
        for (int j = 0; j < 4; j++) C[(size_t)r * N + col0 + (tx << 2) + j] = acc[i][j];
    }
}

// ---------------- output GEMM with epilogue: out = (ctx@W + b)*qmask + qn ----------------
__global__ __launch_bounds__(256) void outgemm_kernel(const float* __restrict__ A,
                                                      const float* __restrict__ Bm,
                                                      const float* __restrict__ bias,
                                                      const float* __restrict__ qn,
                                                      const int* __restrict__ qlen,
                                                      float* __restrict__ C,
                                                      int M, int N, int K) {
    __shared__ float As[16][64];
    __shared__ float Bs[16][64];
    int tid = threadIdx.x;
    int row0 = blockIdx.y * 64;
    int col0 = blockIdx.x * 64;
    int tx = tid & 15, ty = tid >> 4;

    int a_m = tid >> 2;
    int a_k = (tid & 3) << 2;
    int b_k = tid >> 4;
    int b_n = (tid & 15) << 2;

    float acc[4][4];
#pragma unroll
    for (int i = 0; i < 4; i++)
#pragma unroll
        for (int j = 0; j < 4; j++) acc[i][j] = 0.f;

    for (int k0 = 0; k0 < K; k0 += 16) {
        float4 a4 = *(const float4*)(A + (size_t)(row0 + a_m) * K + k0 + a_k);
        As[a_k + 0][a_m] = a4.x;
        As[a_k + 1][a_m] = a4.y;
        As[a_k + 2][a_m] = a4.z;
        As[a_k + 3][a_m] = a4.w;
        *(float4*)(&Bs[b_k][b_n]) = *(const float4*)(Bm + (size_t)(k0 + b_k) * N + col0 + b_n);
        __syncthreads();
#pragma unroll
        for (int k = 0; k < 16; k++) {
            float4 ra = *(const float4*)(&As[k][ty << 2]);
            float4 rb = *(const float4*)(&Bs[k][tx << 2]);
            float raa[4] = {ra.x, ra.y, ra.z, ra.w};
            float rbb[4] = {rb.x, rb.y, rb.z, rb.w};
#pragma unroll
            for (int i = 0; i < 4; i++)
#pragma unroll
                for (int j = 0; j < 4; j++) acc[i][j] += raa[i] * rbb[j];
        }
        __syncthreads();
    }
#pragma unroll
    for (int i = 0; i < 4; i++) {
        int r = row0 + (ty << 2) + i;
        int b = r >> 10;
        int s = r & 1023;
        float keep = (s < qlen[b]) ? 1.f : 0.f;
#pragma unroll
        for (int j = 0; j < 4; j++) {
            int c = col0 + (tx << 2) + j;
            C[(size_t)r * N + c] = (acc[i][j] + bias[c]) * keep + qn[(size_t)r * N + c];
        }
    }
}

// ---------------- fused attention: one CTA per (b, h, 32 q-rows) ----------------
// smem: sQ[32*64] | sK[64*65] | sS[32*1024]  (~152 KB)
__global__ __launch_bounds__(256) void attn_kernel(const float* __restrict__ qp,
                                                   const float* __restrict__ kp,
                                                   const float* __restrict__ vp,
                                                   const int* __restrict__ klen,
                                                   float* __restrict__ attn_out,
                                                   float* __restrict__ ctx) {
    extern __shared__ float sm[];
    float* sQ = sm;                 // 32*64 = 2048
    float* sK = sm + 2048;          // 64*65 = 4160
    float* sS = sm + 2048 + 4160;   // 32*1024 = 32768

    const int b = blockIdx.z;
    const int h = blockIdx.y;
    const int q0 = blockIdx.x * 32;
    const int tid = threadIdx.x;
    const size_t base = (size_t)b * (size_t)(S_ * E_);

    // gather Q (non-standard head split: row = h*64 + s/16, col = (s%16)*64 + d)
    for (int idx = tid; idx < 32 * 64; idx += 256) {
        int i = idx >> 6, d = idx & 63;
        int s = q0 + i;
        sQ[idx] = qp[base + (size_t)((h << 6) + (s >> 4)) * 1024 + ((s & 15) << 6) + d];
    }
    const int kl = klen[b];
    const int trow = tid >> 4;  // 0..15 -> q rows 2*trow, 2*trow+1
    const int tcol = tid & 15;  // t cols tcol*4 .. +3

    // ---- scores = QK^T / 8, masked to 1e-10 ----
    for (int kt = 0; kt < 16; kt++) {
        __syncthreads();
        for (int idx = tid; idx < 64 * 64; idx += 256) {
            int j = idx >> 6, d = idx & 63;
            int t = (kt << 6) + j;
            sK[j * 65 + d] = kp[base + (size_t)((h << 6) + (t >> 4)) * 1024 + ((t & 15) << 6) + d];
        }
        __syncthreads();
        float acc[2][4] = {{0.f, 0.f, 0.f, 0.f}, {0.f, 0.f, 0.f, 0.f}};
#pragma unroll 8
        for (int d = 0; d < 64; d++) {
            float a0 = sQ[(trow * 2) * 64 + d];
            float a1 = sQ[(trow * 2 + 1) * 64 + d];
#pragma unroll
            for (int j = 0; j < 4; j++) {
                float kv = sK[(tcol * 4 + j) * 65 + d];
                acc[0][j] += a0 * kv;
                acc[1][j] += a1 * kv;
            }
        }
#pragma unroll
        for (int i = 0; i < 2; i++)
#pragma unroll
            for (int j = 0; j < 4; j++) {
                int t = (kt << 6) + tcol * 4 + j;
                float sc = acc[i][j] * 0.125f;
                if (t >= kl) sc = 1e-10f;
                sS[(trow * 2 + i) * 1024 + t] = sc;
            }
    }
    __syncthreads();

    // ---- softmax over full rows (8 warps x 4 rows) ----
    {
        int wid = tid >> 5, lane = tid & 31;
        for (int r = wid * 4; r < wid * 4 + 4; r++) {
            float* row = sS + r * 1024;
            float m = -1e30f;
#pragma unroll
            for (int i = 0; i < 32; i++) m = fmaxf(m, row[i * 32 + lane]);
            for (int off = 16; off; off >>= 1) m = fmaxf(m, __shfl_xor_sync(0xffffffffu, m, off));
            float e[32];
            float sum = 0.f;
#pragma unroll
            for (int i = 0; i < 32; i++) { e[i] = __expf(row[i * 32 + lane] - m); sum += e[i]; }
            for (int off = 16; off; off >>= 1) sum += __shfl_xor_sync(0xffffffffu, sum, off);
            float inv = 1.f / sum;
#pragma unroll
            for (int i = 0; i < 32; i++) row[i * 32 + lane] = e[i] * inv;
        }
    }
    __syncthreads();

    // ---- write attention probabilities ----
    if (attn_out) {
        size_t abase = (((size_t)b * H_ + h) * S_ + q0) * (size_t)S_;
        for (int idx = tid; idx < 32 * 1024; idx += 256) attn_out[abase + idx] = sS[idx];
    }

    // ---- ctx = P @ V ----
    float cacc[2][4] = {{0.f, 0.f, 0.f, 0.f}, {0.f, 0.f, 0.f, 0.f}};
    for (int kt = 0; kt < 16; kt++) {
        __syncthreads();
        for (int idx = tid; idx < 64 * 64; idx += 256) {
            int j = idx >> 6, d = idx & 63;
            int t = (kt << 6) + j;
            sK[j * 65 + d] = vp[base + (size_t)((h << 6) + (t >> 4)) * 1024 + ((t & 15) << 6) + d];
        }
        __syncthreads();
#pragma unroll 8
        for (int jj = 0; jj < 64; jj++) {
            float p0 = sS[(trow * 2) * 1024 + (kt << 6) + jj];
            float p1 = sS[(trow * 2 + 1) * 1024 + (kt << 6) + jj];
#pragma unroll
            for (int j = 0; j < 4; j++) {
                float vv = sK[jj * 65 + tcol * 4 + j];
                cacc[0][j] += p0 * vv;
                cacc[1][j] += p1 * vv;
            }
        }
    }
    // write ctx in concat layout: ctx[b, s, h*64 + d]
#pragma unroll
    for (int i = 0; i < 2; i++) {
        int s = q0 + trow * 2 + i;
#pragma unroll
        for (int j = 0; j < 4; j++) {
            int dcol = tcol * 4 + j;
            ctx[((size_t)b * S_ + s) * 1024 + (h << 6) + dcol] = cacc[i][j];
        }
    }
}

// ---------------- launcher ----------------
extern "C" void kernel_launch(void* const* d_in, const int* in_sizes, int n_in,
                              void* d_out, int out_size) {
    const float* query = (const float*)d_in[0];
    const float* key   = (const float*)d_in[1];
    const float* value = (const float*)d_in[2];
    const int*   qlen  = (const int*)d_in[3];
    const int*   klen  = (const int*)d_in[4];
    const float* wq    = (const float*)d_in[5];
    const float* wk    = (const float*)d_in[6];
    const float* wv    = (const float*)d_in[7];
    const float* gamma = (const float*)d_in[8];
    const float* beta  = (const float*)d_in[9];
    const float* outw  = (const float*)d_in[10];
    const float* outb  = (const float*)d_in[11];

    float* out = (float*)d_out;
    const long long n_skip = (long long)B_ * S_ * E_;                      // 4194304
    const long long n_attn = (long long)B_ * H_ * S_ * (long long)S_;     // 67108864
    float* attn_out = ((long long)out_size >= n_skip + n_attn) ? (out + n_skip) : nullptr;

    float *qn, *qp, *kp, *vp, *ctx;
    cudaGetSymbolAddress((void**)&qn,  g_qn);
    cudaGetSymbolAddress((void**)&qp,  g_qp);
    cudaGetSymbolAddress((void**)&kp,  g_kp);
    cudaGetSymbolAddress((void**)&vp,  g_vp);
    cudaGetSymbolAddress((void**)&ctx, g_ctx);

    const int M = B_ * S_;  // 4096
    const int N = E_;       // 1024
    const int K = E_;       // 1024

    // layernorm
    ln_kernel<<<M, 256>>>(query, gamma, beta, qn);

    // projections
    dim3 ggrid(N / 64, M / 64);
    sgemm_kernel<<<ggrid, 256>>>(qn,    wq, qp, M, N, K);
    sgemm_kernel<<<ggrid, 256>>>(key,   wk, kp, M, N, K);
    sgemm_kernel<<<ggrid, 256>>>(value, wv, vp, M, N, K);

    // fused attention
    int smem = (2048 + 64 * 65 + 32 * 1024) * (int)sizeof(float);
    cudaFuncSetAttribute(attn_kernel, cudaFuncAttributeMaxDynamicSharedMemorySize, smem);
    dim3 agrid(S_ / 32, H_, B_);
    attn_kernel<<<agrid, 256, smem>>>(qp, kp, vp, klen, attn_out, ctx);

    // output projection + mask + residual
    outgemm_kernel<<<ggrid, 256>>>(ctx, outw, outb, qn, qlen, out, M, N, K);
}

// round 2
// speedup vs baseline: 1.5876x; 1.5876x over previous
#include <cuda_runtime.h>
#include <cuda_bf16.h>
#include <math.h>

#define B_    4
#define S_    1024
#define E_    1024
#define H_    16
#define DH_   64

// ---------------- scratch ----------------
__device__ float g_qn [B_ * S_ * E_];
__device__ float g_qp [B_ * S_ * E_];
__device__ float g_kp [B_ * S_ * E_];
__device__ float g_vp [B_ * S_ * E_];
__device__ float g_ctx[B_ * S_ * E_];

// ---------------- packed fp32x2 FMA ----------------
__device__ __forceinline__ void ffma2(float2& d, float2 a, float2 b, float2 c) {
    asm("fma.rn.f32x2 %0, %1, %2, %3;"
        : "=l"(reinterpret_cast<unsigned long long&>(d))
        : "l"(reinterpret_cast<unsigned long long&>(a)),
          "l"(reinterpret_cast<unsigned long long&>(b)),
          "l"(reinterpret_cast<unsigned long long&>(c)));
}

// ---------------- layernorm ----------------
__global__ __launch_bounds__(256) void ln_kernel(const float* __restrict__ x,
                                                 const float* __restrict__ gamma,
                                                 const float* __restrict__ beta,
                                                 float* __restrict__ y) {
    __shared__ float red[32];
    int row = blockIdx.x;
    int tid = threadIdx.x;
    const float* xr = x + (size_t)row * 1024;

    float v[4];
    float s = 0.f;
#pragma unroll
    for (int i = 0; i < 4; i++) { v[i] = xr[tid + 256 * i]; s += v[i]; }

    for (int off = 16; off; off >>= 1) s += __shfl_xor_sync(0xffffffffu, s, off);
    int lane = tid & 31, wid = tid >> 5;
    if (lane == 0) red[wid] = s;
    __syncthreads();
    if (wid == 0) {
        float t = (lane < 8) ? red[lane] : 0.f;
        for (int off = 4; off; off >>= 1) t += __shfl_xor_sync(0xffffffffu, t, off);
        if (lane == 0) red[0] = t;
    }
    __syncthreads();
    float mean = red[0] * (1.f / 1024.f);
    __syncthreads();

    float vs = 0.f;
#pragma unroll
    for (int i = 0; i < 4; i++) { float d = v[i] - mean; vs += d * d; }
    for (int off = 16; off; off >>= 1) vs += __shfl_xor_sync(0xffffffffu, vs, off);
    if (lane == 0) red[wid] = vs;
    __syncthreads();
    if (wid == 0) {
        float t = (lane < 8) ? red[lane] : 0.f;
        for (int off = 4; off; off >>= 1) t += __shfl_xor_sync(0xffffffffu, t, off);
        if (lane == 0) red[0] = t;
    }
    __syncthreads();
    float var = red[0] * (1.f / 1024.f);
    float rstd = rsqrtf(var + 1e-5f);

    float* yr = y + (size_t)row * 1024;
#pragma unroll
    for (int i = 0; i < 4; i++) {
        int c = tid + 256 * i;
        yr[c] = (v[i] - mean) * rstd * gamma[c] + beta[c];
    }
}

// ---------------- SGEMM v2: 128x128 tile, 8x8/thread, fp32x2, double-buffered ----------------
// C[M=4096, N=1024] = A @ B, K=1024. EPI: (acc+bias)*qmask + qn
template<bool EPI>
__global__ __launch_bounds__(256) void sgemm2(const float* __restrict__ A,
                                              const float* __restrict__ Bm,
                                              float* __restrict__ C,
                                              const float* __restrict__ bias,
                                              const float* __restrict__ qn,
                                              const int* __restrict__ qlen) {
    __shared__ float As[2][8][128];
    __shared__ float Bs[2][8][128];

    const int tid = threadIdx.x;
    const int tx = tid & 15, ty = tid >> 4;
    const int row0 = blockIdx.y * 128;
    const int col0 = blockIdx.x * 128;

    // global load assignments
    const int ar = tid >> 1;            // 0..127
    const int ak = (tid & 1) << 2;      // 0 or 4
    const int bk = tid >> 5;            // 0..7
    const int bc = (tid & 31) << 2;     // 0..124

    const float* gA = A + (size_t)(row0 + ar) * 1024 + ak;
    const float* gB = Bm + (size_t)bk * 1024 + col0 + bc;

    float2 acc[8][4];
#pragma unroll
    for (int i = 0; i < 8; i++)
#pragma unroll
        for (int j = 0; j < 4; j++) acc[i][j] = make_float2(0.f, 0.f);

    // prologue: load chunk 0
    {
        float4 pa = *(const float4*)gA;
        float4 pb = *(const float4*)gB;
        As[0][ak + 0][ar] = pa.x;
        As[0][ak + 1][ar] = pa.y;
        As[0][ak + 2][ar] = pa.z;
        As[0][ak + 3][ar] = pa.w;
        *(float4*)&Bs[0][bk][bc] = pb;
    }
    __syncthreads();

    const int NIT = 128;  // K/8
    for (int it = 0; it < NIT; it++) {
        const int cur = it & 1;
        float4 pa, pb;
        if (it < NIT - 1) {
            pa = *(const float4*)(gA + (it + 1) * 8);
            pb = *(const float4*)(gB + (size_t)(it + 1) * 8 * 1024);
        }
#pragma unroll
        for (int kk = 0; kk < 8; kk++) {
            float4 a0 = *(const float4*)&As[cur][kk][ty * 8];
            float4 a1 = *(const float4*)&As[cur][kk][ty * 8 + 4];
            float4 b0 = *(const float4*)&Bs[cur][kk][tx * 8];
            float4 b1 = *(const float4*)&Bs[cur][kk][tx * 8 + 4];
            float2 bp[4] = {{b0.x, b0.y}, {b0.z, b0.w}, {b1.x, b1.y}, {b1.z, b1.w}};
            float av[8] = {a0.x, a0.y, a0.z, a0.w, a1.x, a1.y, a1.z, a1.w};
#pragma unroll
            for (int i = 0; i < 8; i++) {
                float2 ad = make_float2(av[i], av[i]);
#pragma unroll
                for (int j = 0; j < 4; j++) ffma2(acc[i][j], ad, bp[j], acc[i][j]);
            }
        }
        if (it < NIT - 1) {
            const int nxt = cur ^ 1;
            As[nxt][ak + 0][ar] = pa.x;
            As[nxt][ak + 1][ar] = pa.y;
            As[nxt][ak + 2][ar] = pa.z;
            As[nxt][ak + 3][ar] = pa.w;
            *(float4*)&Bs[nxt][bk][bc] = pb;
        }
        __syncthreads();
    }

    // epilogue
#pragma unroll
    for (int i = 0; i < 8; i++) {
        int r = row0 + ty * 8 + i;
        float4 o0 = make_float4(acc[i][0].x, acc[i][0].y, acc[i][1].x, acc[i][1].y);
        float4 o1 = make_float4(acc[i][2].x, acc[i][2].y, acc[i][3].x, acc[i][3].y);
        int c = col0 + tx * 8;
        if (EPI) {
            int bb = r >> 10;
            int ss = r & 1023;
            float keep = (ss < qlen[bb]) ? 1.f : 0.f;
            const float4 bi0 = *(const float4*)&bias[c];
            const float4 bi1 = *(const float4*)&bias[c + 4];
            const float4 q0 = *(const float4*)&qn[(size_t)r * 1024 + c];
            const float4 q1 = *(const float4*)&qn[(size_t)r * 1024 + c + 4];
            o0.x = (o0.x + bi0.x) * keep + q0.x;
            o0.y = (o0.y + bi0.y) * keep + q0.y;
            o0.z = (o0.z + bi0.z) * keep + q0.z;
            o0.w = (o0.w + bi0.w) * keep + q0.w;
            o1.x = (o1.x + bi1.x) * keep + q1.x;
            o1.y = (o1.y + bi1.y) * keep + q1.y;
            o1.z = (o1.z + bi1.z) * keep + q1.z;
            o1.w = (o1.w + bi1.w) * keep + q1.w;
        }
        *(float4*)&C[(size_t)r * 1024 + c] = o0;
        *(float4*)&C[(size_t)r * 1024 + c + 4] = o1;
    }
}

// ---------------- attention v2 ----------------
// CTA: (b, h, 32 q-rows), 256 threads.
// smem floats: sQt[64][36] | sKV[256][68] | sS[32][1036]
#define SPAD 1036
#define KTW  68
#define SM_QT   0
#define SM_KV   2304
#define SM_S    (2304 + 17408)
#define SM_TOT  (2304 + 17408 + 32 * SPAD)

__global__ __launch_bounds__(256) void attn2_kernel(const float* __restrict__ qp,
                                                    const float* __restrict__ kp,
                                                    const float* __restrict__ vp,
                                                    const int* __restrict__ klen,
                                                    float* __restrict__ attn_out,
                                                    float* __restrict__ ctx) {
    extern __shared__ float sm[];
    float* sQt = sm + SM_QT;
    float* sKV = sm + SM_KV;
    float* sS  = sm + SM_S;

    const int b = blockIdx.z;
    const int h = blockIdx.y;
    const int q0blk = blockIdx.x * 32;
    const int tid = threadIdx.x;
    const size_t base = (size_t)b * (size_t)(S_ * E_);
    const int kl = klen[b];

    // load Q transposed: sQt[d][i]
    for (int idx = tid; idx < 32 * 64; idx += 256) {
        int i = idx >> 6, d = idx & 63;
        int s = q0blk + i;
        sQt[d * 36 + i] = qp[base + (size_t)((h << 6) + (s >> 4)) * 1024 + ((s & 15) << 6) + d];
    }

    const int qg = tid & 7;   // q0 = qg*4
    const int tg = tid >> 3;  // t0 = tg*8

    // ---- QK: 4 chunks of 256 t ----
    for (int ch = 0; ch < 4; ch++) {
        __syncthreads();
        // load K chunk [256][64] -> sKV[j][d]
#pragma unroll
        for (int it = 0; it < 16; it++) {
            int j = (tid >> 4) + it * 16;
            int d = (tid & 15) << 2;
            int t = ch * 256 + j;
            *(float4*)&sKV[j * KTW + d] =
                *(const float4*)&kp[base + (size_t)((h << 6) + (t >> 4)) * 1024 + ((t & 15) << 6) + d];
        }
        __syncthreads();

        float2 acc[8][2];
#pragma unroll
        for (int j = 0; j < 8; j++) { acc[j][0] = make_float2(0.f, 0.f); acc[j][1] = make_float2(0.f, 0.f); }

#pragma unroll 4
        for (int d = 0; d < 64; d++) {
            float4 qv = *(const float4*)&sQt[d * 36 + qg * 4];
            float2 qa = make_float2(qv.x, qv.y);
            float2 qb = make_float2(qv.z, qv.w);
#pragma unroll
            for (int j = 0; j < 8; j++) {
                float kv = sKV[(tg * 8 + j) * KTW + d];
                float2 kb = make_float2(kv, kv);
                ffma2(acc[j][0], kb, qa, acc[j][0]);
                ffma2(acc[j][1], kb, qb, acc[j][1]);
            }
        }
        // store scores (scaled + masked) to sS[q][t]
#pragma unroll
        for (int j = 0; j < 8; j++) {
            int t = ch * 256 + tg * 8 + j;
            bool ok = (t < kl);
            float s0 = ok ? acc[j][0].x * 0.125f : 1e-10f;
            float s1 = ok ? acc[j][0].y * 0.125f : 1e-10f;
            float s2 = ok ? acc[j][1].x * 0.125f : 1e-10f;
            float s3 = ok ? acc[j][1].y * 0.125f : 1e-10f;
            sS[(qg * 4 + 0) * SPAD + t] = s0;
            sS[(qg * 4 + 1) * SPAD + t] = s1;
            sS[(qg * 4 + 2) * SPAD + t] = s2;
            sS[(qg * 4 + 3) * SPAD + t] = s3;
        }
    }
    __syncthreads();

    // ---- softmax (8 warps x 4 rows) + write attn probs ----
    {
        int wid = tid >> 5, lane = tid & 31;
        size_t abase = 0;
        if (attn_out) abase = (((size_t)b * H_ + h) * S_ + q0blk) * (size_t)S_;
        for (int r = wid * 4; r < wid * 4 + 4; r++) {
            float* row = sS + r * SPAD;
            float m = -1e30f;
#pragma unroll
            for (int i = 0; i < 32; i++) m = fmaxf(m, row[i * 32 + lane]);
            for (int off = 16; off; off >>= 1) m = fmaxf(m, __shfl_xor_sync(0xffffffffu, m, off));
            float e[32];
            float sum = 0.f;
#pragma unroll
            for (int i = 0; i < 32; i++) { e[i] = __expf(row[i * 32 + lane] - m); sum += e[i]; }
            for (int off = 16; off; off >>= 1) sum += __shfl_xor_sync(0xffffffffu, sum, off);
            float inv = 1.f / sum;
#pragma unroll
            for (int i = 0; i < 32; i++) {
                float p = e[i] * inv;
                row[i * 32 + lane] = p;
                if (attn_out) attn_out[abase + (size_t)r * S_ + i * 32 + lane] = p;
            }
        }
    }

    // ---- PV: ctx[32][64] = P[32][1024] @ V[1024][64], 8 chunks of 128 k ----
    const int pqg = tid & 7;   // q rows: pqg + 8m
    const int dg = tid >> 3;   // d0 = dg*2
    float2 cacc[4];
#pragma unroll
    for (int m = 0; m < 4; m++) cacc[m] = make_float2(0.f, 0.f);

    for (int ch = 0; ch < 8; ch++) {
        __syncthreads();
        // load V chunk [128][64] -> sKV[j][d]
#pragma unroll
        for (int it = 0; it < 8; it++) {
            int j = (tid >> 4) + it * 16;
            int d = (tid & 15) << 2;
            int t = ch * 128 + j;
            *(float4*)&sKV[j * KTW + d] =
                *(const float4*)&vp[base + (size_t)((h << 6) + (t >> 4)) * 1024 + ((t & 15) << 6) + d];
        }
        __syncthreads();

        const int kbase = ch * 128;
#pragma unroll 2
        for (int kk = 0; kk < 128; kk += 4) {
            float4 pm[4];
#pragma unroll
            for (int m = 0; m < 4; m++)
                pm[m] = *(const float4*)&sS[(pqg + 8 * m) * SPAD + kbase + kk];
#pragma unroll
            for (int c = 0; c < 4; c++) {
                float2 v2 = *(const float2*)&sKV[(kk + c) * KTW + dg * 2];
                float pc0 = (c == 0) ? pm[0].x : (c == 1) ? pm[0].y : (c == 2) ? pm[0].z : pm[0].w;
                float pc1 = (c == 0) ? pm[1].x : (c == 1) ? pm[1].y : (c == 2) ? pm[1].z : pm[1].w;
                float pc2 = (c == 0) ? pm[2].x : (c == 1) ? pm[2].y : (c == 2) ? pm[2].z : pm[2].w;
                float pc3 = (c == 0) ? pm[3].x : (c == 1) ? pm[3].y : (c == 2) ? pm[3].z : pm[3].w;
                ffma2(cacc[0], make_float2(pc0, pc0), v2, cacc[0]);
                ffma2(cacc[1], make_float2(pc1, pc1), v2, cacc[1]);
                ffma2(cacc[2], make_float2(pc2, pc2), v2, cacc[2]);
                ffma2(cacc[3], make_float2(pc3, pc3), v2, cacc[3]);
            }
        }
    }
    // write ctx[b, s, h*64 + d]
#pragma unroll
    for (int m = 0; m < 4; m++) {
        int s = q0blk + pqg + 8 * m;
        *(float2*)&ctx[((size_t)b * S_ + s) * 1024 + (h << 6) + dg * 2] = cacc[m];
    }
}

// ---------------- launcher ----------------
extern "C" void kernel_launch(void* const* d_in, const int* in_sizes, int n_in,
                              void* d_out, int out_size) {
    const float* query = (const float*)d_in[0];
    const float* key   = (const float*)d_in[1];
    const float* value = (const float*)d_in[2];
    const int*   qlen  = (const int*)d_in[3];
    const int*   klen  = (const int*)d_in[4];
    const float* wq    = (const float*)d_in[5];
    const float* wk    = (const float*)d_in[6];
    const float* wv    = (const float*)d_in[7];
    const float* gamma = (const float*)d_in[8];
    const float* beta  = (const float*)d_in[9];
    const float* outw  = (const float*)d_in[10];
    const float* outb  = (const float*)d_in[11];

    float* out = (float*)d_out;
    const long long n_skip = (long long)B_ * S_ * E_;
    const long long n_attn = (long long)B_ * H_ * S_ * (long long)S_;
    float* attn_out = ((long long)out_size >= n_skip + n_attn) ? (out + n_skip) : nullptr;

    float *qn, *qp, *kp, *vp, *ctx;
    cudaGetSymbolAddress((void**)&qn,  g_qn);
    cudaGetSymbolAddress((void**)&qp,  g_qp);
    cudaGetSymbolAddress((void**)&kp,  g_kp);
    cudaGetSymbolAddress((void**)&vp,  g_vp);
    cudaGetSymbolAddress((void**)&ctx, g_ctx);

    // layernorm
    ln_kernel<<<B_ * S_, 256>>>(query, gamma, beta, qn);

    // projections: 128x128 tiles
    dim3 ggrid(1024 / 128, 4096 / 128);
    sgemm2<false><<<ggrid, 256>>>(qn,    wq, qp, nullptr, nullptr, nullptr);
    sgemm2<false><<<ggrid, 256>>>(key,   wk, kp, nullptr, nullptr, nullptr);
    sgemm2<false><<<ggrid, 256>>>(value, wv, vp, nullptr, nullptr, nullptr);

    // fused attention
    int smem = SM_TOT * (int)sizeof(float);
    cudaFuncSetAttribute(attn2_kernel, cudaFuncAttributeMaxDynamicSharedMemorySize, smem);
    dim3 agrid(S_ / 32, H_, B_);
    attn2_kernel<<<agrid, 256, smem>>>(qp, kp, vp, klen, attn_out, ctx);

    // output projection + mask + residual
    sgemm2<true><<<ggrid, 256>>>(ctx, outw, out, outb, qn, qlen);
}

// round 4
// speedup vs baseline: 2.3107x; 1.4554x over previous
#include <cuda_runtime.h>
#include <cuda_bf16.h>
#include <math.h>
#include <stdint.h>

#define B_    4
#define S_    1024
#define E_    1024
#define H_    16
#define DH_   64

// ---------------- scratch ----------------
__device__ float g_qn [B_ * S_ * E_];
__device__ float g_qp [B_ * S_ * E_];
__device__ float g_kp [B_ * S_ * E_];
__device__ float g_vp [B_ * S_ * E_];
__device__ float g_ctx[B_ * S_ * E_];
__device__ __nv_bfloat16 g_ah[B_ * S_ * E_];   // A split hi
__device__ __nv_bfloat16 g_al[B_ * S_ * E_];   // A split lo
__device__ __nv_bfloat16 g_wh[E_ * E_];        // W^T split hi
__device__ __nv_bfloat16 g_wl[E_ * E_];        // W^T split lo

// ---------------- PTX helpers (portable sm_80-era; compiles for compute_103) ----------------
__device__ __forceinline__ uint32_t smem_u32(const void* p) {
    uint32_t a;
    asm("{ .reg .u64 t; cvta.to.shared.u64 t, %1; cvt.u32.u64 %0, t; }" : "=r"(a) : "l"(p));
    return a;
}
__device__ __forceinline__ void cp_async16(uint32_t s, const void* g) {
    asm volatile("cp.async.cg.shared.global [%0], [%1], 16;" :: "r"(s), "l"(g));
}
__device__ __forceinline__ void cp_commit() { asm volatile("cp.async.commit_group;" ::: "memory"); }
template<int N> __device__ __forceinline__ void cp_wait() { asm volatile("cp.async.wait_group %0;" :: "n"(N) : "memory"); }

__device__ __forceinline__ void ldmx4(uint32_t* r, uint32_t addr) {
    asm volatile("ldmatrix.sync.aligned.m8n8.x4.shared.b16 {%0,%1,%2,%3}, [%4];"
        : "=r"(r[0]), "=r"(r[1]), "=r"(r[2]), "=r"(r[3]) : "r"(addr));
}
__device__ __forceinline__ void mma16816(float* d, const uint32_t* a, const uint32_t* b) {
    asm volatile("mma.sync.aligned.m16n8k16.row.col.f32.bf16.bf16.f32 "
        "{%0,%1,%2,%3}, {%4,%5,%6,%7}, {%8,%9}, {%0,%1,%2,%3};"
        : "+f"(d[0]), "+f"(d[1]), "+f"(d[2]), "+f"(d[3])
        : "r"(a[0]), "r"(a[1]), "r"(a[2]), "r"(a[3]), "r"(b[0]), "r"(b[1]));
}

// ---------------- packed fp32x2 FMA (attention) ----------------
__device__ __forceinline__ void ffma2(float2& d, float2 a, float2 b, float2 c) {
    asm("fma.rn.f32x2 %0, %1, %2, %3;"
        : "=l"(reinterpret_cast<unsigned long long&>(d))
        : "l"(reinterpret_cast<unsigned long long&>(a)),
          "l"(reinterpret_cast<unsigned long long&>(b)),
          "l"(reinterpret_cast<unsigned long long&>(c)));
}

// ---------------- layernorm ----------------
__global__ __launch_bounds__(256) void ln_kernel(const float* __restrict__ x,
                                                 const float* __restrict__ gamma,
                                                 const float* __restrict__ beta,
                                                 float* __restrict__ y) {
    __shared__ float red[32];
    int row = blockIdx.x;
    int tid = threadIdx.x;
    const float* xr = x + (size_t)row * 1024;

    float v[4];
    float s = 0.f;
#pragma unroll
    for (int i = 0; i < 4; i++) { v[i] = xr[tid + 256 * i]; s += v[i]; }

    for (int off = 16; off; off >>= 1) s += __shfl_xor_sync(0xffffffffu, s, off);
    int lane = tid & 31, wid = tid >> 5;
    if (lane == 0) red[wid] = s;
    __syncthreads();
    if (wid == 0) {
        float t = (lane < 8) ? red[lane] : 0.f;
        for (int off = 4; off; off >>= 1) t += __shfl_xor_sync(0xffffffffu, t, off);
        if (lane == 0) red[0] = t;
    }
    __syncthreads();
    float mean = red[0] * (1.f / 1024.f);
    __syncthreads();

    float vs = 0.f;
#pragma unroll
    for (int i = 0; i < 4; i++) { float d = v[i] - mean; vs += d * d; }
    for (int off = 16; off; off >>= 1) vs += __shfl_xor_sync(0xffffffffu, vs, off);
    if (lane == 0) red[wid] = vs;
    __syncthreads();
    if (wid == 0) {
        float t = (lane < 8) ? red[lane] : 0.f;
        for (int off = 4; off; off >>= 1) t += __shfl_xor_sync(0xffffffffu, t, off);
        if (lane == 0) red[0] = t;
    }
    __syncthreads();
    float var = red[0] * (1.f / 1024.f);
    float rstd = rsqrtf(var + 1e-5f);

    float* yr = y + (size_t)row * 1024;
#pragma unroll
    for (int i = 0; i < 4; i++) {
        int c = tid + 256 * i;
        yr[c] = (v[i] - mean) * rstd * gamma[c] + beta[c];
    }
}

// ---------------- fp32 -> bf16 hi/lo split ----------------
__global__ __launch_bounds__(256) void split_kernel(const float* __restrict__ x,
                                                    __nv_bfloat16* __restrict__ hi,
                                                    __nv_bfloat16* __restrict__ lo,
                                                    int n4) {
    int i = blockIdx.x * 256 + threadIdx.x;
    if (i >= n4) return;
    float4 v = *(const float4*)(x + (size_t)i * 4);
    float f[4] = {v.x, v.y, v.z, v.w};
    __nv_bfloat16 h[4], l[4];
#pragma unroll
    for (int j = 0; j < 4; j++) {
        h[j] = __float2bfloat16_rn(f[j]);
        l[j] = __float2bfloat16_rn(f[j] - __bfloat162float(h[j]));
    }
    *(uint2*)(hi + (size_t)i * 4) = *(uint2*)h;
    *(uint2*)(lo + (size_t)i * 4) = *(uint2*)l;
}

// ---------------- W[1024x1024] -> W^T split hi/lo ----------------
__global__ __launch_bounds__(256) void transpose_split_kernel(const float* __restrict__ W,
                                                              __nv_bfloat16* __restrict__ th,
                                                              __nv_bfloat16* __restrict__ tl) {
    __shared__ float t[32][33];
    int bx = blockIdx.x * 32;  // n
    int by = blockIdx.y * 32;  // k
    int x = threadIdx.x & 31, y = threadIdx.x >> 5;
#pragma unroll
    for (int i = 0; i < 32; i += 8)
        t[y + i][x] = W[(size_t)(by + y + i) * 1024 + bx + x];
    __syncthreads();
#pragma unroll
    for (int i = 0; i < 32; i += 8) {
        int n = bx + y + i, k = by + x;
        float v = t[x][y + i];
        __nv_bfloat16 h = __float2bfloat16_rn(v);
        __nv_bfloat16 l = __float2bfloat16_rn(v - __bfloat162float(h));
        th[(size_t)n * 1024 + k] = h;
        tl[(size_t)n * 1024 + k] = l;
    }
}

// ---------------- HMMA bf16x3 GEMM ----------------
// C[4096,1024] = A @ B.  A pre-split bf16 hi/lo [m][k]; B pre-transposed+split Bt[n][k].
// Block 128x128, BK=32, 2-stage cp.async.  8 warps, warp grid 4(M)x2(N), warp tile 32x64.
#define LDK 40                                   // padded halves per smem row
static constexpr int MAT_H  = 128 * LDK;         // halves per matrix (5120)
static constexpr int GEMM_SMEM = 2 * 4 * MAT_H * 2;  // 81920 bytes

template<bool EPI>
__global__ __launch_bounds__(256) void hgemm(const __nv_bfloat16* __restrict__ Ah,
                                             const __nv_bfloat16* __restrict__ Al,
                                             const __nv_bfloat16* __restrict__ Bth,
                                             const __nv_bfloat16* __restrict__ Btl,
                                             float* __restrict__ C,
                                             const float* __restrict__ bias,
                                             const float* __restrict__ qn,
                                             const int* __restrict__ qlen) {
    extern __shared__ __nv_bfloat16 smb[];
    const int tid = threadIdx.x;
    const int wid = tid >> 5, lane = tid & 31;
    const int row0 = blockIdx.y * 128;
    const int col0 = blockIdx.x * 128;
    const uint32_t sbase = smem_u32(smb);

    const __nv_bfloat16* gp0 = Ah  + (size_t)row0 * 1024;
    const __nv_bfloat16* gp1 = Al  + (size_t)row0 * 1024;
    const __nv_bfloat16* gp2 = Bth + (size_t)col0 * 1024;
    const __nv_bfloat16* gp3 = Btl + (size_t)col0 * 1024;

    // per-thread load slots: c = tid + 256*i -> row c/4, 16B quad c%4
    const int lr = tid >> 2;
    const int lq = (tid & 3) * 8;

    auto load_stage = [&](int st, int kt) {
        uint32_t sb = sbase + (uint32_t)st * 4 * MAT_H * 2;
        const __nv_bfloat16* gs[4] = {gp0 + kt * 32, gp1 + kt * 32, gp2 + kt * 32, gp3 + kt * 32};
#pragma unroll
        for (int m = 0; m < 4; m++) {
#pragma unroll
            for (int i = 0; i < 2; i++) {
                int r = lr + i * 64;
                cp_async16(sb + (uint32_t)(m * MAT_H + r * LDK + lq) * 2,
                           gs[m] + (size_t)r * 1024 + lq);
            }
        }
    };

    load_stage(0, 0);
    cp_commit();

    float acc[2][8][4];
#pragma unroll
    for (int mt = 0; mt < 2; mt++)
#pragma unroll
        for (int nt = 0; nt < 8; nt++)
#pragma unroll
            for (int j = 0; j < 4; j++) acc[mt][nt][j] = 0.f;

    const int warp_m = (wid & 3) * 32;
    const int warp_n = (wid >> 2) * 64;

    // precomputed ldmatrix lane offsets (in halves)
    const uint32_t a_off = (uint32_t)((warp_m + (lane & 15)) * LDK + (lane >> 4) * 8);
    const uint32_t b_off = (uint32_t)((warp_n + (lane >> 4) * 8 + (lane & 7)) * LDK + ((lane >> 3) & 1) * 8);

    for (int kt = 0; kt < 32; kt++) {
        const int st = kt & 1;
        if (kt + 1 < 32) {
            load_stage(st ^ 1, kt + 1);
            cp_commit();
            cp_wait<1>();
        } else {
            cp_wait<0>();
        }
        __syncthreads();

        const uint32_t Abase = sbase + (uint32_t)st * 4 * MAT_H * 2;
        const uint32_t Bbase = Abase + 2 * MAT_H * 2;
#pragma unroll
        for (int ks = 0; ks < 2; ks++) {
            const uint32_t kadd = (uint32_t)(ks * 16) * 2;
            uint32_t a_h[2][4], a_l[2][4];
#pragma unroll
            for (int mt = 0; mt < 2; mt++) {
                uint32_t off = (a_off + (uint32_t)(mt * 16) * LDK) * 2 + kadd;
                ldmx4(a_h[mt], Abase + off);
                ldmx4(a_l[mt], Abase + MAT_H * 2 + off);
            }
#pragma unroll
            for (int np = 0; np < 4; np++) {
                uint32_t b_h[4], b_l[4];
                uint32_t off = (b_off + (uint32_t)(np * 16) * LDK) * 2 + kadd;
                ldmx4(b_h, Bbase + off);
                ldmx4(b_l, Bbase + MAT_H * 2 + off);
#pragma unroll
                for (int mt = 0; mt < 2; mt++) {
                    mma16816(acc[mt][np * 2 + 0], a_h[mt], b_h + 0);
                    mma16816(acc[mt][np * 2 + 0], a_h[mt], b_l + 0);
                    mma16816(acc[mt][np * 2 + 0], a_l[mt], b_h + 0);
                    mma16816(acc[mt][np * 2 + 1], a_h[mt], b_h + 2);
                    mma16816(acc[mt][np * 2 + 1], a_h[mt], b_l + 2);
                    mma16816(acc[mt][np * 2 + 1], a_l[mt], b_h + 2);
                }
            }
        }
        __syncthreads();
    }

    // epilogue: frag (mt, nt): rows r, r+8; cols c, c+1
#pragma unroll
    for (int mt = 0; mt < 2; mt++) {
        int r0i = row0 + warp_m + mt * 16 + (lane >> 2);
#pragma unroll
        for (int half = 0; half < 2; half++) {
            int r = r0i + half * 8;
            float keep = 1.f;
            if (EPI) {
                int bb = r >> 10, ss = r & 1023;
                keep = (ss < qlen[bb]) ? 1.f : 0.f;
            }
#pragma unroll
            for (int nt = 0; nt < 8; nt++) {
                int c = col0 + warp_n + nt * 8 + (lane & 3) * 2;
                float2 o = make_float2(acc[mt][nt][half * 2 + 0], acc[mt][nt][half * 2 + 1]);
                if (EPI) {
                    const float2 bi = *(const float2*)&bias[c];
                    const float2 q2 = *(const float2*)&qn[(size_t)r * 1024 + c];
                    o.x = (o.x + bi.x) * keep + q2.x;
                    o.y = (o.y + bi.y) * keep + q2.y;
                }
                *(float2*)&C[(size_t)r * 1024 + c] = o;
            }
        }
    }
}

// ---------------- attention (unchanged, known-good) ----------------
#define SPAD 1036
#define KTW  68
#define SM_QT   0
#define SM_KV   2304
#define SM_S    (2304 + 17408)
#define SM_TOT  (2304 + 17408 + 32 * SPAD)

__global__ __launch_bounds__(256) void attn2_kernel(const float* __restrict__ qp,
                                                    const float* __restrict__ kp,
                                                    const float* __restrict__ vp,
                                                    const int* __restrict__ klen,
                                                    float* __restrict__ attn_out,
                                                    float* __restrict__ ctx) {
    extern __shared__ float sm[];
    float* sQt = sm + SM_QT;
    float* sKV = sm + SM_KV;
    float* sS  = sm + SM_S;

    const int b = blockIdx.z;
    const int h = blockIdx.y;
    const int q0blk = blockIdx.x * 32;
    const int tid = threadIdx.x;
    const size_t base = (size_t)b * (size_t)(S_ * E_);
    const int kl = klen[b];

    for (int idx = tid; idx < 32 * 64; idx += 256) {
        int i = idx >> 6, d = idx & 63;
        int s = q0blk + i;
        sQt[d * 36 + i] = qp[base + (size_t)((h << 6) + (s >> 4)) * 1024 + ((s & 15) << 6) + d];
    }

    const int qg = tid & 7;
    const int tg = tid >> 3;

    for (int ch = 0; ch < 4; ch++) {
        __syncthreads();
#pragma unroll
        for (int it = 0; it < 16; it++) {
            int j = (tid >> 4) + it * 16;
            int d = (tid & 15) << 2;
            int t = ch * 256 + j;
            *(float4*)&sKV[j * KTW + d] =
                *(const float4*)&kp[base + (size_t)((h << 6) + (t >> 4)) * 1024 + ((t & 15) << 6) + d];
        }
        __syncthreads();

        float2 acc[8][2];
#pragma unroll
        for (int j = 0; j < 8; j++) { acc[j][0] = make_float2(0.f, 0.f); acc[j][1] = make_float2(0.f, 0.f); }

#pragma unroll 4
        for (int d = 0; d < 64; d++) {
            float4 qv = *(const float4*)&sQt[d * 36 + qg * 4];
            float2 qa = make_float2(qv.x, qv.y);
            float2 qb = make_float2(qv.z, qv.w);
#pragma unroll
            for (int j = 0; j < 8; j++) {
                float kv = sKV[(tg * 8 + j) * KTW + d];
                float2 kb = make_float2(kv, kv);
                ffma2(acc[j][0], kb, qa, acc[j][0]);
                ffma2(acc[j][1], kb, qb, acc[j][1]);
            }
        }
#pragma unroll
        for (int j = 0; j < 8; j++) {
            int t = ch * 256 + tg * 8 + j;
            bool ok = (t < kl);
            sS[(qg * 4 + 0) * SPAD + t] = ok ? acc[j][0].x * 0.125f : 1e-10f;
            sS[(qg * 4 + 1) * SPAD + t] = ok ? acc[j][0].y * 0.125f : 1e-10f;
            sS[(qg * 4 + 2) * SPAD + t] = ok ? acc[j][1].x * 0.125f : 1e-10f;
            sS[(qg * 4 + 3) * SPAD + t] = ok ? acc[j][1].y * 0.125f : 1e-10f;
        }
    }
    __syncthreads();

    {
        int wid = tid >> 5, lane = tid & 31;
        size_t abase = 0;
        if (attn_out) abase = (((size_t)b * H_ + h) * S_ + q0blk) * (size_t)S_;
        for (int r = wid * 4; r < wid * 4 + 4; r++) {
            float* row = sS + r * SPAD;
            float m = -1e30f;
#pragma unroll
            for (int i = 0; i < 32; i++) m = fmaxf(m, row[i * 32 + lane]);
            for (int off = 16; off; off >>= 1) m = fmaxf(m, __shfl_xor_sync(0xffffffffu, m, off));
            float e[32];
            float sum = 0.f;
#pragma unroll
            for (int i = 0; i < 32; i++) { e[i] = __expf(row[i * 32 + lane] - m); sum += e[i]; }
            for (int off = 16; off; off >>= 1) sum += __shfl_xor_sync(0xffffffffu, sum, off);
            float inv = 1.f / sum;
#pragma unroll
            for (int i = 0; i < 32; i++) {
                float p = e[i] * inv;
                row[i * 32 + lane] = p;
                if (attn_out) attn_out[abase + (size_t)r * S_ + i * 32 + lane] = p;
            }
        }
    }

    const int pqg = tid & 7;
    const int dg = tid >> 3;
    float2 cacc[4];
#pragma unroll
    for (int m = 0; m < 4; m++) cacc[m] = make_float2(0.f, 0.f);

    for (int ch = 0; ch < 8; ch++) {
        __syncthreads();
#pragma unroll
        for (int it = 0; it < 8; it++) {
            int j = (tid >> 4) + it * 16;
            int d = (tid & 15) << 2;
            int t = ch * 128 + j;
            *(float4*)&sKV[j * KTW + d] =
                *(const float4*)&vp[base + (size_t)((h << 6) + (t >> 4)) * 1024 + ((t & 15) << 6) + d];
        }
        __syncthreads();

        const int kbase = ch * 128;
#pragma unroll 2
        for (int kk = 0; kk < 128; kk += 4) {
            float4 pm[4];
#pragma unroll
            for (int m = 0; m < 4; m++)
                pm[m] = *(const float4*)&sS[(pqg + 8 * m) * SPAD + kbase + kk];
#pragma unroll
            for (int c = 0; c < 4; c++) {
                float2 v2 = *(const float2*)&sKV[(kk + c) * KTW + dg * 2];
                float pc0 = (c == 0) ? pm[0].x : (c == 1) ? pm[0].y : (c == 2) ? pm[0].z : pm[0].w;
                float pc1 = (c == 0) ? pm[1].x : (c == 1) ? pm[1].y : (c == 2) ? pm[1].z : pm[1].w;
                float pc2 = (c == 0) ? pm[2].x : (c == 1) ? pm[2].y : (c == 2) ? pm[2].z : pm[2].w;
                float pc3 = (c == 0) ? pm[3].x : (c == 1) ? pm[3].y : (c == 2) ? pm[3].z : pm[3].w;
                ffma2(cacc[0], make_float2(pc0, pc0), v2, cacc[0]);
                ffma2(cacc[1], make_float2(pc1, pc1), v2, cacc[1]);
                ffma2(cacc[2], make_float2(pc2, pc2), v2, cacc[2]);
                ffma2(cacc[3], make_float2(pc3, pc3), v2, cacc[3]);
            }
        }
    }
#pragma unroll
    for (int m = 0; m < 4; m++) {
        int s = q0blk + pqg + 8 * m;
        *(float2*)&ctx[((size_t)b * S_ + s) * 1024 + (h << 6) + dg * 2] = cacc[m];
    }
}

// ---------------- launcher ----------------
extern "C" void kernel_launch(void* const* d_in, const int* in_sizes, int n_in,
                              void* d_out, int out_size) {
    const float* query = (const float*)d_in[0];
    const float* key   = (const float*)d_in[1];
    const float* value = (const float*)d_in[2];
    const int*   qlen  = (const int*)d_in[3];
    const int*   klen  = (const int*)d_in[4];
    const float* wq    = (const float*)d_in[5];
    const float* wk    = (const float*)d_in[6];
    const float* wv    = (const float*)d_in[7];
    const float* gamma = (const float*)d_in[8];
    const float* beta  = (const float*)d_in[9];
    const float* outw  = (const float*)d_in[10];
    const float* outb  = (const float*)d_in[11];

    float* out = (float*)d_out;
    const long long n_skip = (long long)B_ * S_ * E_;
    const long long n_attn = (long long)B_ * H_ * S_ * (long long)S_;
    float* attn_out = ((long long)out_size >= n_skip + n_attn) ? (out + n_skip) : nullptr;

    float *qn, *qp, *kp, *vp, *ctx;
    __nv_bfloat16 *ah, *al, *wh, *wl;
    cudaGetSymbolAddress((void**)&qn,  g_qn);
    cudaGetSymbolAddress((void**)&qp,  g_qp);
    cudaGetSymbolAddress((void**)&kp,  g_kp);
    cudaGetSymbolAddress((void**)&vp,  g_vp);
    cudaGetSymbolAddress((void**)&ctx, g_ctx);
    cudaGetSymbolAddress((void**)&ah,  g_ah);
    cudaGetSymbolAddress((void**)&al,  g_al);
    cudaGetSymbolAddress((void**)&wh,  g_wh);
    cudaGetSymbolAddress((void**)&wl,  g_wl);

    cudaFuncSetAttribute(hgemm<false>, cudaFuncAttributeMaxDynamicSharedMemorySize, GEMM_SMEM);
    cudaFuncSetAttribute(hgemm<true>,  cudaFuncAttributeMaxDynamicSharedMemorySize, GEMM_SMEM);
    cudaFuncSetAttribute(attn2_kernel, cudaFuncAttributeMaxDynamicSharedMemorySize, SM_TOT * (int)sizeof(float));

    const int nA4 = B_ * S_ * E_ / 4;
    dim3 tgrid(32, 32), tblk(256);
    dim3 ggrid(1024 / 128, 4096 / 128);

    // layernorm
    ln_kernel<<<B_ * S_, 256>>>(query, gamma, beta, qn);

    // Q projection
    split_kernel<<<nA4 / 256, 256>>>(qn, ah, al, nA4);
    transpose_split_kernel<<<tgrid, tblk>>>(wq, wh, wl);
    hgemm<false><<<ggrid, 256, GEMM_SMEM>>>(ah, al, wh, wl, qp, nullptr, nullptr, nullptr);

    // K projection
    split_kernel<<<nA4 / 256, 256>>>(key, ah, al, nA4);
    transpose_split_kernel<<<tgrid, tblk>>>(wk, wh, wl);
    hgemm<false><<<ggrid, 256, GEMM_SMEM>>>(ah, al, wh, wl, kp, nullptr, nullptr, nullptr);

    // V projection
    split_kernel<<<nA4 / 256, 256>>>(value, ah, al, nA4);
    transpose_split_kernel<<<tgrid, tblk>>>(wv, wh, wl);
    hgemm<false><<<ggrid, 256, GEMM_SMEM>>>(ah, al, wh, wl, vp, nullptr, nullptr, nullptr);

    // fused attention
    dim3 agrid(S_ / 32, H_, B_);
    attn2_kernel<<<agrid, 256, SM_TOT * (int)sizeof(float)>>>(qp, kp, vp, klen, attn_out, ctx);

    // output projection + mask + residual
    split_kernel<<<nA4 / 256, 256>>>(ctx, ah, al, nA4);
    transpose_split_kernel<<<tgrid, tblk>>>(outw, wh, wl);
    hgemm<true><<<ggrid, 256, GEMM_SMEM>>>(ah, al, wh, wl, out, outb, qn, qlen);
}

// round 5
// speedup vs baseline: 4.2423x; 1.8360x over previous
#include <cuda_runtime.h>
#include <cuda_bf16.h>
#include <math.h>
#include <stdint.h>

#define B_    4
#define S_    1024
#define E_    1024
#define H_    16
#define DH_   64

// ---------------- scratch ----------------
__device__ float g_qn [B_ * S_ * E_];
__device__ __nv_bfloat16 g_qh[B_ * S_ * E_];
__device__ __nv_bfloat16 g_ql[B_ * S_ * E_];
__device__ __nv_bfloat16 g_kh[B_ * S_ * E_];
__device__ __nv_bfloat16 g_kl[B_ * S_ * E_];
__device__ __nv_bfloat16 g_vh[B_ * S_ * E_];
__device__ __nv_bfloat16 g_vl[B_ * S_ * E_];
__device__ __nv_bfloat16 g_vth[B_ * S_ * E_];  // V^T per (b,h): [d][t]
__device__ __nv_bfloat16 g_vtl[B_ * S_ * E_];
__device__ __nv_bfloat16 g_ah[B_ * S_ * E_];   // GEMM A hi (splits / ctx)
__device__ __nv_bfloat16 g_al[B_ * S_ * E_];
__device__ __nv_bfloat16 g_wh[E_ * E_];
__device__ __nv_bfloat16 g_wl[E_ * E_];

// ---------------- PTX helpers ----------------
__device__ __forceinline__ uint32_t smem_u32(const void* p) {
    uint32_t a;
    asm("{ .reg .u64 t; cvta.to.shared.u64 t, %1; cvt.u32.u64 %0, t; }" : "=r"(a) : "l"(p));
    return a;
}
__device__ __forceinline__ void cp_async16(uint32_t s, const void* g) {
    asm volatile("cp.async.cg.shared.global [%0], [%1], 16;" :: "r"(s), "l"(g));
}
__device__ __forceinline__ void cp_commit() { asm volatile("cp.async.commit_group;" ::: "memory"); }
template<int N> __device__ __forceinline__ void cp_wait() { asm volatile("cp.async.wait_group %0;" :: "n"(N) : "memory"); }

__device__ __forceinline__ void ldmx4(uint32_t* r, uint32_t addr) {
    asm volatile("ldmatrix.sync.aligned.m8n8.x4.shared.b16 {%0,%1,%2,%3}, [%4];"
        : "=r"(r[0]), "=r"(r[1]), "=r"(r[2]), "=r"(r[3]) : "r"(addr));
}
__device__ __forceinline__ void mma16816(float* d, const uint32_t* a, const uint32_t* b) {
    asm volatile("mma.sync.aligned.m16n8k16.row.col.f32.bf16.bf16.f32 "
        "{%0,%1,%2,%3}, {%4,%5,%6,%7}, {%8,%9}, {%0,%1,%2,%3};"
        : "+f"(d[0]), "+f"(d[1]), "+f"(d[2]), "+f"(d[3])
        : "r"(a[0]), "r"(a[1]), "r"(a[2]), "r"(a[3]), "r"(b[0]), "r"(b[1]));
}
__device__ __forceinline__ uint32_t pack_bf2(__nv_bfloat16 a, __nv_bfloat16 b) {
    uint32_t r;
    uint16_t ua = *(uint16_t*)&a, ub = *(uint16_t*)&b;
    r = (uint32_t)ua | ((uint32_t)ub << 16);
    return r;
}

// ---------------- layernorm ----------------
__global__ __launch_bounds__(256) void ln_kernel(const float* __restrict__ x,
                                                 const float* __restrict__ gamma,
                                                 const float* __restrict__ beta,
                                                 float* __restrict__ y) {
    __shared__ float red[32];
    int row = blockIdx.x;
    int tid = threadIdx.x;
    const float* xr = x + (size_t)row * 1024;

    float v[4];
    float s = 0.f;
#pragma unroll
    for (int i = 0; i < 4; i++) { v[i] = xr[tid + 256 * i]; s += v[i]; }

    for (int off = 16; off; off >>= 1) s += __shfl_xor_sync(0xffffffffu, s, off);
    int lane = tid & 31, wid = tid >> 5;
    if (lane == 0) red[wid] = s;
    __syncthreads();
    if (wid == 0) {
        float t = (lane < 8) ? red[lane] : 0.f;
        for (int off = 4; off; off >>= 1) t += __shfl_xor_sync(0xffffffffu, t, off);
        if (lane == 0) red[0] = t;
    }
    __syncthreads();
    float mean = red[0] * (1.f / 1024.f);
    __syncthreads();

    float vs = 0.f;
#pragma unroll
    for (int i = 0; i < 4; i++) { float d = v[i] - mean; vs += d * d; }
    for (int off = 16; off; off >>= 1) vs += __shfl_xor_sync(0xffffffffu, vs, off);
    if (lane == 0) red[wid] = vs;
    __syncthreads();
    if (wid == 0) {
        float t = (lane < 8) ? red[lane] : 0.f;
        for (int off = 4; off; off >>= 1) t += __shfl_xor_sync(0xffffffffu, t, off);
        if (lane == 0) red[0] = t;
    }
    __syncthreads();
    float var = red[0] * (1.f / 1024.f);
    float rstd = rsqrtf(var + 1e-5f);

    float* yr = y + (size_t)row * 1024;
#pragma unroll
    for (int i = 0; i < 4; i++) {
        int c = tid + 256 * i;
        yr[c] = (v[i] - mean) * rstd * gamma[c] + beta[c];
    }
}

// ---------------- fp32 -> bf16 hi/lo split ----------------
__global__ __launch_bounds__(256) void split_kernel(const float* __restrict__ x,
                                                    __nv_bfloat16* __restrict__ hi,
                                                    __nv_bfloat16* __restrict__ lo,
                                                    int n4) {
    int i = blockIdx.x * 256 + threadIdx.x;
    if (i >= n4) return;
    float4 v = *(const float4*)(x + (size_t)i * 4);
    float f[4] = {v.x, v.y, v.z, v.w};
    __nv_bfloat16 h[4], l[4];
#pragma unroll
    for (int j = 0; j < 4; j++) {
        h[j] = __float2bfloat16_rn(f[j]);
        l[j] = __float2bfloat16_rn(f[j] - __bfloat162float(h[j]));
    }
    *(uint2*)(hi + (size_t)i * 4) = *(uint2*)h;
    *(uint2*)(lo + (size_t)i * 4) = *(uint2*)l;
}

// ---------------- W -> W^T split hi/lo ----------------
__global__ __launch_bounds__(256) void transpose_split_kernel(const float* __restrict__ W,
                                                              __nv_bfloat16* __restrict__ th,
                                                              __nv_bfloat16* __restrict__ tl) {
    __shared__ float t[32][33];
    int bx = blockIdx.x * 32;
    int by = blockIdx.y * 32;
    int x = threadIdx.x & 31, y = threadIdx.x >> 5;
#pragma unroll
    for (int i = 0; i < 32; i += 8)
        t[y + i][x] = W[(size_t)(by + y + i) * 1024 + bx + x];
    __syncthreads();
#pragma unroll
    for (int i = 0; i < 32; i += 8) {
        int n = bx + y + i, k = by + x;
        float v = t[x][y + i];
        __nv_bfloat16 h = __float2bfloat16_rn(v);
        __nv_bfloat16 l = __float2bfloat16_rn(v - __bfloat162float(h));
        th[(size_t)n * 1024 + k] = h;
        tl[(size_t)n * 1024 + k] = l;
    }
}

// ---------------- HMMA bf16x3 GEMM ----------------
// MODE 0: write bf16 hi/lo pair outputs (Oh, Ol). MODE 1: fp32 out with bias/mask/residual.
#define LDK 40
static constexpr int MAT_H  = 128 * LDK;
static constexpr int GEMM_SMEM = 2 * 4 * MAT_H * 2;

template<int MODE>
__global__ __launch_bounds__(256) void hgemm(const __nv_bfloat16* __restrict__ Ah,
                                             const __nv_bfloat16* __restrict__ Al,
                                             const __nv_bfloat16* __restrict__ Bth,
                                             const __nv_bfloat16* __restrict__ Btl,
                                             float* __restrict__ C,
                                             __nv_bfloat16* __restrict__ Oh,
                                             __nv_bfloat16* __restrict__ Ol,
                                             const float* __restrict__ bias,
                                             const float* __restrict__ qn,
                                             const int* __restrict__ qlen) {
    extern __shared__ __nv_bfloat16 smb[];
    const int tid = threadIdx.x;
    const int wid = tid >> 5, lane = tid & 31;
    const int row0 = blockIdx.y * 128;
    const int col0 = blockIdx.x * 128;
    const uint32_t sbase = smem_u32(smb);

    const __nv_bfloat16* gp0 = Ah  + (size_t)row0 * 1024;
    const __nv_bfloat16* gp1 = Al  + (size_t)row0 * 1024;
    const __nv_bfloat16* gp2 = Bth + (size_t)col0 * 1024;
    const __nv_bfloat16* gp3 = Btl + (size_t)col0 * 1024;

    const int lr = tid >> 2;
    const int lq = (tid & 3) * 8;

    auto load_stage = [&](int st, int kt) {
        uint32_t sb = sbase + (uint32_t)st * 4 * MAT_H * 2;
        const __nv_bfloat16* gs[4] = {gp0 + kt * 32, gp1 + kt * 32, gp2 + kt * 32, gp3 + kt * 32};
#pragma unroll
        for (int m = 0; m < 4; m++) {
#pragma unroll
            for (int i = 0; i < 2; i++) {
                int r = lr + i * 64;
                cp_async16(sb + (uint32_t)(m * MAT_H + r * LDK + lq) * 2,
                           gs[m] + (size_t)r * 1024 + lq);
            }
        }
    };

    load_stage(0, 0);
    cp_commit();

    float acc[2][8][4];
#pragma unroll
    for (int mt = 0; mt < 2; mt++)
#pragma unroll
        for (int nt = 0; nt < 8; nt++)
#pragma unroll
            for (int j = 0; j < 4; j++) acc[mt][nt][j] = 0.f;

    const int warp_m = (wid & 3) * 32;
    const int warp_n = (wid >> 2) * 64;

    const uint32_t a_off = (uint32_t)((warp_m + (lane & 15)) * LDK + (lane >> 4) * 8);
    const uint32_t b_off = (uint32_t)((warp_n + (lane >> 4) * 8 + (lane & 7)) * LDK + ((lane >> 3) & 1) * 8);

    for (int kt = 0; kt < 32; kt++) {
        const int st = kt & 1;
        if (kt + 1 < 32) {
            load_stage(st ^ 1, kt + 1);
            cp_commit();
            cp_wait<1>();
        } else {
            cp_wait<0>();
        }
        __syncthreads();

        const uint32_t Abase = sbase + (uint32_t)st * 4 * MAT_H * 2;
        const uint32_t Bbase = Abase + 2 * MAT_H * 2;
#pragma unroll
        for (int ks = 0; ks < 2; ks++) {
            const uint32_t kadd = (uint32_t)(ks * 16) * 2;
            uint32_t a_h[2][4], a_l[2][4];
#pragma unroll
            for (int mt = 0; mt < 2; mt++) {
                uint32_t off = (a_off + (uint32_t)(mt * 16) * LDK) * 2 + kadd;
                ldmx4(a_h[mt], Abase + off);
                ldmx4(a_l[mt], Abase + MAT_H * 2 + off);
            }
#pragma unroll
            for (int np = 0; np < 4; np++) {
                uint32_t b_h[4], b_l[4];
                uint32_t off = (b_off + (uint32_t)(np * 16) * LDK) * 2 + kadd;
                ldmx4(b_h, Bbase + off);
                ldmx4(b_l, Bbase + MAT_H * 2 + off);
#pragma unroll
                for (int mt = 0; mt < 2; mt++) {
                    mma16816(acc[mt][np * 2 + 0], a_h[mt], b_h + 0);
                    mma16816(acc[mt][np * 2 + 0], a_h[mt], b_l + 0);
                    mma16816(acc[mt][np * 2 + 0], a_l[mt], b_h + 0);
                    mma16816(acc[mt][np * 2 + 1], a_h[mt], b_h + 2);
                    mma16816(acc[mt][np * 2 + 1], a_h[mt], b_l + 2);
                    mma16816(acc[mt][np * 2 + 1], a_l[mt], b_h + 2);
                }
            }
        }
        __syncthreads();
    }

#pragma unroll
    for (int mt = 0; mt < 2; mt++) {
        int r0i = row0 + warp_m + mt * 16 + (lane >> 2);
#pragma unroll
        for (int half = 0; half < 2; half++) {
            int r = r0i + half * 8;
            float keep = 1.f;
            if (MODE == 1) {
                int bb = r >> 10, ss = r & 1023;
                keep = (ss < qlen[bb]) ? 1.f : 0.f;
            }
#pragma unroll
            for (int nt = 0; nt < 8; nt++) {
                int c = col0 + warp_n + nt * 8 + (lane & 3) * 2;
                float v0 = acc[mt][nt][half * 2 + 0];
                float v1 = acc[mt][nt][half * 2 + 1];
                if (MODE == 1) {
                    const float2 bi = *(const float2*)&bias[c];
                    const float2 q2 = *(const float2*)&qn[(size_t)r * 1024 + c];
                    v0 = (v0 + bi.x) * keep + q2.x;
                    v1 = (v1 + bi.y) * keep + q2.y;
                    *(float2*)&C[(size_t)r * 1024 + c] = make_float2(v0, v1);
                } else {
                    __nv_bfloat16 h0 = __float2bfloat16_rn(v0);
                    __nv_bfloat16 h1 = __float2bfloat16_rn(v1);
                    __nv_bfloat16 l0 = __float2bfloat16_rn(v0 - __bfloat162float(h0));
                    __nv_bfloat16 l1 = __float2bfloat16_rn(v1 - __bfloat162float(h1));
                    *(uint32_t*)&Oh[(size_t)r * 1024 + c] = pack_bf2(h0, h1);
                    *(uint32_t*)&Ol[(size_t)r * 1024 + c] = pack_bf2(l0, l1);
                }
            }
        }
    }
}

// ---------------- V^T: vp[b, h*64+t/16, (t%16)*64+d] -> vt[(b*16+h)*64+d][t] ----------------
__global__ __launch_bounds__(256) void vtrans_kernel(const __nv_bfloat16* __restrict__ vh,
                                                     const __nv_bfloat16* __restrict__ vl,
                                                     __nv_bfloat16* __restrict__ vth,
                                                     __nv_bfloat16* __restrict__ vtl) {
    __shared__ __nv_bfloat16 sm[2][64 * 66];
    const int tt = blockIdx.x;     // 16 t-tiles
    const int h  = blockIdx.y;
    const int b  = blockIdx.z;
    const int tid = threadIdx.x;

    const size_t in_off = ((size_t)(b * 1024 + h * 64 + tt * 4)) * 1024;
    const __nv_bfloat16* src[2] = {vh + in_off, vl + in_off};
#pragma unroll
    for (int pl = 0; pl < 2; pl++) {
        for (int it = 0; it < 8; it++) {
            int p = tid + 256 * it;          // pair index 0..2047
            int i = p >> 5;                  // t-in-tile
            int d = (p & 31) * 2;
            uint32_t v = *(const uint32_t*)(src[pl] + (size_t)i * 64 + d);
            *(uint32_t*)&sm[pl][i * 66 + d] = v;
        }
    }
    __syncthreads();
    const size_t out_off = ((size_t)((b * 16 + h) * 64)) * 1024 + tt * 64;
    __nv_bfloat16* dst[2] = {vth + out_off, vtl + out_off};
#pragma unroll
    for (int pl = 0; pl < 2; pl++) {
        for (int it = 0; it < 8; it++) {
            int w = tid + 256 * it;          // 0..2047: d*32 + j
            int d = w >> 5;
            int j = (w & 31) * 2;
            __nv_bfloat16 a = sm[pl][j * 66 + d];
            __nv_bfloat16 bb = sm[pl][(j + 1) * 66 + d];
            *(uint32_t*)(dst[pl] + (size_t)d * 1024 + j) = pack_bf2(a, bb);
        }
    }
}

// ---------------- fused attention v3 (HMMA) ----------------
// CTA: (qblk32, h, b). smem halves layout:
//   sQ hi/lo: 32x72 each          @ 0 / 2304
//   sK bufs:  2 x 2planes x 128x72 @ 4608  (buf stride 18432, plane stride 9216)
//   sE hi/lo: 32x1048 each        @ 41472 / 75008
//   sZ (32 floats)                @ byte 217088
#define EPAD 1048
static constexpr int A_SQH = 0;
static constexpr int A_SQL = 2304;
static constexpr int A_SK  = 4608;
static constexpr int A_SEH = 41472;
static constexpr int A_SEL = 75008;
static constexpr int ATTN_SMEM = 217088 + 128;

__global__ __launch_bounds__(256) void attn3_kernel(const __nv_bfloat16* __restrict__ qh,
                                                    const __nv_bfloat16* __restrict__ ql,
                                                    const __nv_bfloat16* __restrict__ kh,
                                                    const __nv_bfloat16* __restrict__ kl_,
                                                    const __nv_bfloat16* __restrict__ vth,
                                                    const __nv_bfloat16* __restrict__ vtl,
                                                    const int* __restrict__ klen,
                                                    float* __restrict__ attn_out,
                                                    __nv_bfloat16* __restrict__ ctx_h,
                                                    __nv_bfloat16* __restrict__ ctx_l) {
    extern __shared__ __nv_bfloat16 smb[];
    const uint32_t sb = smem_u32(smb);
    float* sZ = (float*)(smb + 108544);

    const int b = blockIdx.z;
    const int h = blockIdx.y;
    const int q0 = blockIdx.x * 32;
    const int tid = threadIdx.x;
    const int wid = tid >> 5, lane = tid & 31;
    const int kl = klen[b];
    const int nact = (kl + 127) >> 7;       // active 128-chunks

    const size_t base = (size_t)b * (S_ * E_);

    // ---- load Q (32 rows x 64) hi/lo via cp.async ----
    {
        int row = tid >> 3, seg = (tid & 7) * 8;
        int s = q0 + row;
        size_t ga = base + (size_t)((h << 6) + (s >> 4)) * 1024 + ((s & 15) << 6) + seg;
        cp_async16(sb + (uint32_t)(A_SQH + row * 72 + seg) * 2, qh + ga);
        cp_async16(sb + (uint32_t)(A_SQL + row * 72 + seg) * 2, ql + ga);
    }

    // ---- K chunk 0 ----
    auto load_k = [&](int ch, int buf) {
        uint32_t kb = sb + (uint32_t)(A_SK + buf * 18432) * 2;
#pragma unroll
        for (int i = 0; i < 4; i++) {
            int idx = tid + i * 256;
            int j = idx >> 3, seg = (idx & 7) * 8;
            int t = ch * 128 + j;
            size_t ga = base + (size_t)((h << 6) + (t >> 4)) * 1024 + ((t & 15) << 6) + seg;
            uint32_t sa = kb + (uint32_t)(j * 72 + seg) * 2;
            cp_async16(sa, kh + ga);
            cp_async16(sa + 9216 * 2, kl_ + ga);
        }
    };
    auto load_v = [&](int ch, int buf) {
        uint32_t vb = sb + (uint32_t)(A_SK + buf * 18432) * 2;
        size_t vbase = ((size_t)((b * 16 + h) * 64)) * 1024 + ch * 128;
#pragma unroll
        for (int i = 0; i < 4; i++) {
            int idx = tid + i * 256;
            int d = idx >> 4, seg = (idx & 15) * 8;
            size_t ga = vbase + (size_t)d * 1024 + seg;
            uint32_t sa = vb + (uint32_t)(d * 136 + seg) * 2;
            cp_async16(sa, vth + ga);
            cp_async16(sa + 9216 * 2, vtl + ga);
        }
    };

    load_k(0, 0);
    cp_commit();

    // ---- fill masked region of sE with 1.0 ----
    {
        int t0 = nact * 128;
        int npairs = (1024 - t0) >> 1;
        if (npairs > 0) {
            uint32_t onepair = pack_bf2(__float2bfloat16_rn(1.f), __float2bfloat16_rn(1.f));
            for (int idx = tid; idx < 32 * npairs; idx += 256) {
                int r = idx / npairs;
                int p = idx - r * npairs;
                int t = t0 + p * 2;
                *(uint32_t*)&smb[A_SEH + r * EPAD + t] = onepair;
                *(uint32_t*)&smb[A_SEL + r * EPAD + t] = 0u;
            }
        }
    }

    const int mt = wid & 1;        // m16 tile
    const int ng = wid >> 1;       // n-group of 32 (QK) / 16 (PV)

    const uint32_t qa_off = (uint32_t)((mt * 16 + (lane & 15)) * 72 + (lane >> 4) * 8);
    const uint32_t kb_off = (uint32_t)((ng * 32 + (lane >> 4) * 8 + (lane & 7)) * 72 + ((lane >> 3) & 1) * 8);

    // ---- QK chunks ----
    for (int ch = 0; ch < nact; ch++) {
        cp_wait<0>();
        __syncthreads();
        if (ch + 1 < nact) { load_k(ch + 1, (ch + 1) & 1); cp_commit(); }

        const uint32_t Kb = sb + (uint32_t)(A_SK + (ch & 1) * 18432) * 2;
        float acc[4][4];
#pragma unroll
        for (int j = 0; j < 4; j++)
#pragma unroll
            for (int k = 0; k < 4; k++) acc[j][k] = 0.f;

#pragma unroll
        for (int ks = 0; ks < 4; ks++) {
            uint32_t a_h[4], a_l[4];
            uint32_t aoff = (qa_off + ks * 16) * 2;
            ldmx4(a_h, sb + A_SQH * 2 + aoff);
            ldmx4(a_l, sb + A_SQL * 2 + aoff);
#pragma unroll
            for (int np = 0; np < 2; np++) {
                uint32_t b_h[4], b_l[4];
                uint32_t boff = (kb_off + np * 16 * 72 + ks * 16) * 2;
                ldmx4(b_h, Kb + boff);
                ldmx4(b_l, Kb + 9216 * 2 + boff);
                mma16816(acc[np * 2 + 0], a_h, b_h + 0);
                mma16816(acc[np * 2 + 0], a_h, b_l + 0);
                mma16816(acc[np * 2 + 0], a_l, b_h + 0);
                mma16816(acc[np * 2 + 1], a_h, b_h + 2);
                mma16816(acc[np * 2 + 1], a_h, b_l + 2);
                mma16816(acc[np * 2 + 1], a_l, b_h + 2);
            }
        }

        // exp + store to sE
        int r1 = mt * 16 + (lane >> 2);
#pragma unroll
        for (int j = 0; j < 4; j++) {
            int c = ch * 128 + ng * 32 + j * 8 + (lane & 3) * 2;
#pragma unroll
            for (int half = 0; half < 2; half++) {
                int r = r1 + half * 8;
                float e0 = (c < kl)     ? __expf(acc[j][half * 2 + 0] * 0.125f) : 1.f;
                float e1 = (c + 1 < kl) ? __expf(acc[j][half * 2 + 1] * 0.125f) : 1.f;
                __nv_bfloat16 h0 = __float2bfloat16_rn(e0);
                __nv_bfloat16 h1 = __float2bfloat16_rn(e1);
                __nv_bfloat16 l0 = __float2bfloat16_rn(e0 - __bfloat162float(h0));
                __nv_bfloat16 l1 = __float2bfloat16_rn(e1 - __bfloat162float(h1));
                *(uint32_t*)&smb[A_SEH + r * EPAD + c] = pack_bf2(h0, h1);
                *(uint32_t*)&smb[A_SEL + r * EPAD + c] = pack_bf2(l0, l1);
            }
        }
    }
    cp_wait<0>();
    __syncthreads();

    // prefetch V chunk 0 (overlaps Z pass + attn write)
    load_v(0, 0);
    cp_commit();

    // ---- row sums Z -> invZ ----
    {
        for (int r = wid * 4; r < wid * 4 + 4; r++) {
            float z = 0.f;
#pragma unroll
            for (int i = 0; i < 16; i++) {
                int t = lane * 2 + i * 64;
                uint32_t ph = *(uint32_t*)&smb[A_SEH + r * EPAD + t];
                uint32_t pl = *(uint32_t*)&smb[A_SEL + r * EPAD + t];
                __nv_bfloat162 vh2 = *(__nv_bfloat162*)&ph;
                __nv_bfloat162 vl2 = *(__nv_bfloat162*)&pl;
                z += __bfloat162float(vh2.x) + __bfloat162float(vl2.x);
                z += __bfloat162float(vh2.y) + __bfloat162float(vl2.y);
            }
            for (int off = 16; off; off >>= 1) z += __shfl_xor_sync(0xffffffffu, z, off);
            if (lane == 0) sZ[r] = 1.f / z;
        }
    }
    __syncthreads();

    // ---- write attention probabilities ----
    if (attn_out) {
        size_t abase = (((size_t)b * H_ + h) * S_ + q0) * (size_t)S_;
        for (int r = wid * 4; r < wid * 4 + 4; r++) {
            float invZ = sZ[r];
            float* orow = attn_out + abase + (size_t)r * S_;
#pragma unroll
            for (int i = 0; i < 16; i++) {
                int t = lane * 2 + i * 64;
                uint32_t ph = *(uint32_t*)&smb[A_SEH + r * EPAD + t];
                uint32_t pl = *(uint32_t*)&smb[A_SEL + r * EPAD + t];
                __nv_bfloat162 vh2 = *(__nv_bfloat162*)&ph;
                __nv_bfloat162 vl2 = *(__nv_bfloat162*)&pl;
                float p0 = (__bfloat162float(vh2.x) + __bfloat162float(vl2.x)) * invZ;
                float p1 = (__bfloat162float(vh2.y) + __bfloat162float(vl2.y)) * invZ;
                *(float2*)&orow[t] = make_float2(p0, p1);
            }
        }
    }

    // ---- PV: ctx[32][64] = E @ V  (V^T tiles), bf16x3 ----
    const uint32_t ea_base = (uint32_t)((mt * 16 + (lane & 15)) * EPAD + (lane >> 4) * 8);
    const uint32_t vb_off = (uint32_t)((ng * 16 + (lane >> 4) * 8 + (lane & 7)) * 136 + ((lane >> 3) & 1) * 8);

    float cacc[2][4];
#pragma unroll
    for (int j = 0; j < 2; j++)
#pragma unroll
        for (int k = 0; k < 4; k++) cacc[j][k] = 0.f;

    for (int ch = 0; ch < 8; ch++) {
        cp_wait<0>();
        __syncthreads();
        if (ch + 1 < 8) { load_v(ch + 1, (ch + 1) & 1); cp_commit(); }

        const uint32_t Vb = sb + (uint32_t)(A_SK + (ch & 1) * 18432) * 2;
#pragma unroll
        for (int ks = 0; ks < 8; ks++) {
            uint32_t a_h[4], a_l[4];
            uint32_t aoff = (ea_base + ch * 128 + ks * 16) * 2;
            ldmx4(a_h, sb + A_SEH * 2 + aoff);
            ldmx4(a_l, sb + A_SEL * 2 + aoff);
            uint32_t b_h[4], b_l[4];
            uint32_t boff = (vb_off + ks * 16) * 2;
            ldmx4(b_h, Vb + boff);
            ldmx4(b_l, Vb + 9216 * 2 + boff);
            mma16816(cacc[0], a_h, b_h + 0);
            mma16816(cacc[0], a_h, b_l + 0);
            mma16816(cacc[0], a_l, b_h + 0);
            mma16816(cacc[1], a_h, b_h + 2);
            mma16816(cacc[1], a_h, b_l + 2);
            mma16816(cacc[1], a_l, b_h + 2);
        }
    }

    // ---- ctx write: scale by invZ, split bf16 hi/lo, layout [b*1024+s][h*64+d] ----
    {
        int r1 = mt * 16 + (lane >> 2);
#pragma unroll
        for (int j = 0; j < 2; j++) {
            int c = ng * 16 + j * 8 + (lane & 3) * 2;
#pragma unroll
            for (int half = 0; half < 2; half++) {
                int r = r1 + half * 8;
                float invZ = sZ[r];
                float v0 = cacc[j][half * 2 + 0] * invZ;
                float v1 = cacc[j][half * 2 + 1] * invZ;
                __nv_bfloat16 h0 = __float2bfloat16_rn(v0);
                __nv_bfloat16 h1 = __float2bfloat16_rn(v1);
                __nv_bfloat16 l0 = __float2bfloat16_rn(v0 - __bfloat162float(h0));
                __nv_bfloat16 l1 = __float2bfloat16_rn(v1 - __bfloat162float(h1));
                size_t oa = (size_t)(b * 1024 + q0 + r) * 1024 + (h << 6) + c;
                *(uint32_t*)&ctx_h[oa] = pack_bf2(h0, h1);
                *(uint32_t*)&ctx_l[oa] = pack_bf2(l0, l1);
            }
        }
    }
}

// ---------------- launcher ----------------
extern "C" void kernel_launch(void* const* d_in, const int* in_sizes, int n_in,
                              void* d_out, int out_size) {
    const float* query = (const float*)d_in[0];
    const float* key   = (const float*)d_in[1];
    const float* value = (const float*)d_in[2];
    const int*   qlen  = (const int*)d_in[3];
    const int*   klen  = (const int*)d_in[4];
    const float* wq    = (const float*)d_in[5];
    const float* wk    = (const float*)d_in[6];
    const float* wv    = (const float*)d_in[7];
    const float* gamma = (const float*)d_in[8];
    const float* beta  = (const float*)d_in[9];
    const float* outw  = (const float*)d_in[10];
    const float* outb  = (const float*)d_in[11];

    float* out = (float*)d_out;
    const long long n_skip = (long long)B_ * S_ * E_;
    const long long n_attn = (long long)B_ * H_ * S_ * (long long)S_;
    float* attn_out = ((long long)out_size >= n_skip + n_attn) ? (out + n_skip) : nullptr;

    float* qn;
    __nv_bfloat16 *qh, *ql, *kh, *kl_, *vh, *vl, *vth, *vtl, *ah, *al, *wh, *wl;
    cudaGetSymbolAddress((void**)&qn,  g_qn);
    cudaGetSymbolAddress((void**)&qh,  g_qh);
    cudaGetSymbolAddress((void**)&ql,  g_ql);
    cudaGetSymbolAddress((void**)&kh,  g_kh);
    cudaGetSymbolAddress((void**)&kl_, g_kl);
    cudaGetSymbolAddress((void**)&vh,  g_vh);
    cudaGetSymbolAddress((void**)&vl,  g_vl);
    cudaGetSymbolAddress((void**)&vth, g_vth);
    cudaGetSymbolAddress((void**)&vtl, g_vtl);
    cudaGetSymbolAddress((void**)&ah,  g_ah);
    cudaGetSymbolAddress((void**)&al,  g_al);
    cudaGetSymbolAddress((void**)&wh,  g_wh);
    cudaGetSymbolAddress((void**)&wl,  g_wl);

    cudaFuncSetAttribute(hgemm<0>, cudaFuncAttributeMaxDynamicSharedMemorySize, GEMM_SMEM);
    cudaFuncSetAttribute(hgemm<1>, cudaFuncAttributeMaxDynamicSharedMemorySize, GEMM_SMEM);
    cudaFuncSetAttribute(attn3_kernel, cudaFuncAttributeMaxDynamicSharedMemorySize, ATTN_SMEM);

    const int nA4 = B_ * S_ * E_ / 4;
    dim3 tgrid(32, 32), tblk(256);
    dim3 ggrid(1024 / 128, 4096 / 128);

    ln_kernel<<<B_ * S_, 256>>>(query, gamma, beta, qn);

    // Q projection -> bf16 hi/lo
    split_kernel<<<nA4 / 256, 256>>>(qn, ah, al, nA4);
    transpose_split_kernel<<<tgrid, tblk>>>(wq, wh, wl);
    hgemm<0><<<ggrid, 256, GEMM_SMEM>>>(ah, al, wh, wl, nullptr, qh, ql, nullptr, nullptr, nullptr);

    // K projection
    split_kernel<<<nA4 / 256, 256>>>(key, ah, al, nA4);
    transpose_split_kernel<<<tgrid, tblk>>>(wk, wh, wl);
    hgemm<0><<<ggrid, 256, GEMM_SMEM>>>(ah, al, wh, wl, nullptr, kh, kl_, nullptr, nullptr, nullptr);

    // V projection
    split_kernel<<<nA4 / 256, 256>>>(value, ah, al, nA4);
    transpose_split_kernel<<<tgrid, tblk>>>(wv, wh, wl);
    hgemm<0><<<ggrid, 256, GEMM_SMEM>>>(ah, al, wh, wl, nullptr, vh, vl, nullptr, nullptr, nullptr);

    // V transpose per (b,h)
    dim3 vgrid(16, H_, B_);
    vtrans_kernel<<<vgrid, 256>>>(vh, vl, vth, vtl);

    // fused attention (writes ctx split directly into ah/al)
    dim3 agrid(S_ / 32, H_, B_);
    attn3_kernel<<<agrid, 256, ATTN_SMEM>>>(qh, ql, kh, kl_, vth, vtl, klen, attn_out, ah, al);

    // output projection + mask + residual
    transpose_split_kernel<<<tgrid, tblk>>>(outw, wh, wl);
    hgemm<1><<<ggrid, 256, GEMM_SMEM>>>(ah, al, wh, wl, out, nullptr, nullptr, outb, qn, qlen);
}